// round 5
// baseline (speedup 1.0000x reference)
#include <cuda_runtime.h>
#include <mma.h>
using namespace nvcuda;

#define M_NODES 1024
#define TJ 128
#define UP 136            // row stride (floats); 136*4=544 B, multiple of 32B
#define NTHREADS 256

// scratch (device globals: no allocation allowed)
__device__ float g_pe_i[M_NODES * 64];
__device__ float g_pe_jT[64 * M_NODES];   // transposed: [c][j]

__device__ __forceinline__ float silu_f(float v) {
    return __fdividef(v, 1.0f + __expf(-v));
}
__device__ __forceinline__ float tf32r(float v) {
    unsigned r; asm("cvt.rna.tf32.f32 %0, %1;" : "=r"(r) : "f"(v));
    return __uint_as_float(r);
}

__global__ void pe_kernel(const float* __restrict__ h, const float* __restrict__ We1) {
    int id = blockIdx.x * blockDim.x + threadIdx.x;   // 65536 threads
    int i = id >> 6, k = id & 63;
    const float* hr = h + i * 64;
    float a0 = 0.f, a1 = 0.f;
#pragma unroll 8
    for (int c = 0; c < 64; c++) {
        float hv = hr[c];
        a0 += hv * We1[c * 64 + k];
        a1 += hv * We1[(64 + c) * 64 + k];
    }
    g_pe_i[id] = a0;
    g_pe_jT[k * M_NODES + i] = a1;
}

// SMEM layout (float offsets; all multiples of 8 -> 32B aligned)
#define OFF_W2    0                 // 4096 (tf32-rounded)
#define OFF_WX1   4096              // 4096 (tf32-rounded)
#define OFF_BA2   8192              // 512 bias panel GEMM B (col-major, ld 64)
#define OFF_BAX   8704              // 512 bias panel GEMM C
#define OFF_ONES  9216              // 128 ones panel (row-major 8x16, ld 16)
#define OFF_UT    9344              // 64*136 = 8704 (u, later v; redm/redx after loop)
#define OFF_MT    18048             // 8704
#define OFF_VEC   26752             // peib,w128,w129,wx2,be2 = 320
#define OFF_GEO   27072             // 2*640 = 1280 (mis/gs reuse at end)
#define OFF_SELF  28352             // u_self 64 + m_self 64
#define SMEM_FLOATS 28480
#define SMEM_BYTES (SMEM_FLOATS * 4)

// One 64k x 128j GEMM: D = silu(W^T @ src + b), W col-major in SMEM (ld 64),
// src/dst row-major [c or k][j] with ld UP. Warp w: kw=(w&3)*16, jw=(w>>2)*64.
template<bool ROUND>
__device__ __forceinline__ void gemm_wmma(const float* __restrict__ Ws,
                                          const float* __restrict__ biasP,
                                          const float* __restrict__ ones,
                                          const float* __restrict__ src,
                                          float* __restrict__ dst,
                                          int kw, int jw)
{
    wmma::fragment<wmma::accumulator, 16, 16, 8, float> cf[4];
#pragma unroll
    for (int t = 0; t < 4; t++) wmma::fill_fragment(cf[t], 0.0f);
    wmma::fragment<wmma::matrix_a, 16, 16, 8, wmma::precision::tf32, wmma::col_major> af;
    wmma::fragment<wmma::matrix_b, 16, 16, 8, wmma::precision::tf32, wmma::row_major> bf;
#pragma unroll
    for (int c0 = 0; c0 < 64; c0 += 8) {
        wmma::load_matrix_sync(af, Ws + kw + c0 * 64, 64);
#pragma unroll
        for (int t = 0; t < 4; t++) {
            wmma::load_matrix_sync(bf, src + c0 * UP + jw + 16 * t, UP);
            wmma::mma_sync(cf[t], af, bf, cf[t]);
        }
    }
    // bias: one extra k-step (biasP column 0 = b, ones row 0 = 1)
    wmma::load_matrix_sync(af, biasP + kw, 64);
    wmma::load_matrix_sync(bf, ones, 16);
#pragma unroll
    for (int t = 0; t < 4; t++) wmma::mma_sync(cf[t], af, bf, cf[t]);
#pragma unroll
    for (int t = 0; t < 4; t++) {
#pragma unroll
        for (int e = 0; e < cf[t].num_elements; e++) {
            float v = silu_f(cf[t].x[e]);
            cf[t].x[e] = ROUND ? tf32r(v) : v;
        }
        wmma::store_matrix_sync(dst + kw * UP + jw + 16 * t, cf[t], UP, wmma::mem_row_major);
    }
}

__global__ void __launch_bounds__(NTHREADS, 2) egnn_main(
    const float* __restrict__ x, const float* __restrict__ a,
    const float* __restrict__ h,
    const float* __restrict__ We1, const float* __restrict__ be1,
    const float* __restrict__ We2, const float* __restrict__ be2,
    const float* __restrict__ Wx1, const float* __restrict__ bx1,
    const float* __restrict__ Wx2, const float* __restrict__ bx2,
    const float* __restrict__ Wh1, const float* __restrict__ bh1,
    const float* __restrict__ Wh2, const float* __restrict__ bh2,
    float* __restrict__ out)
{
    extern __shared__ float sm[];
    float* W2s   = sm + OFF_W2;
    float* Wx1s  = sm + OFF_WX1;
    float* bA2   = sm + OFF_BA2;
    float* bAX   = sm + OFF_BAX;
    float* ones  = sm + OFF_ONES;
    float* uT    = sm + OFF_UT;
    float* mT    = sm + OFF_MT;
    float* peib  = sm + OFF_VEC;
    float* w128s = peib + 64;
    float* w129s = w128s + 64;
    float* wx2s  = w129s + 64;
    float* be2s  = wx2s + 64;
    float* u_self = sm + OFF_SELF;
    float* m_self = u_self + 64;

    const int tid = threadIdx.x;
    const int i = blockIdx.x;

    for (int e = tid; e < 4096; e += NTHREADS) {
        W2s[e]  = tf32r(We2[e]);
        Wx1s[e] = tf32r(Wx1[e]);
    }
    for (int e = tid; e < 512; e += NTHREADS) {
        int kk = e >> 6, m = e & 63;
        bA2[e] = (kk == 0) ? tf32r(be2[m]) : 0.f;
        bAX[e] = (kk == 0) ? tf32r(bx1[m]) : 0.f;
    }
    if (tid < 128) ones[tid] = (tid < 16) ? 1.0f : 0.0f;
    if (tid < 64) {
        peib[tid]  = g_pe_i[i * 64 + tid] + be1[tid];
        w128s[tid] = We1[128 * 64 + tid];
        w129s[tid] = We1[129 * 64 + tid];
        wx2s[tid]  = Wx2[tid];
        be2s[tid]  = be2[tid];
    }
    const float xi0 = x[i * 3 + 0], xi1 = x[i * 3 + 1], xi2 = x[i * 3 + 2];
    const float bx2v = bx2[0];

    // geometry for tile 0 into geo buffer 0
    if (tid < 128) {
        float* g0 = sm + OFF_GEO;
        float xj0 = x[tid * 3 + 0], xj1 = x[tid * 3 + 1], xj2 = x[tid * 3 + 2];
        float dx = xi0 - xj0, dy = xi1 - xj1, dz = xi2 - xj2;
        g0[256 + tid] = dx; g0[384 + tid] = dy; g0[512 + tid] = dz;
        g0[tid] = dx * dx + dy * dy + dz * dz;
        g0[128 + tid] = a[i * M_NODES + tid];
    }
    __syncthreads();

    // self-edge u (for m_i diagonal correction): d2=0, a=a_ii
    if (tid < 64) {
        float a_ii = a[i * M_NODES + i];
        float pre = peib[tid] + g_pe_jT[tid * M_NODES + i] + a_ii * w129s[tid];
        u_self[tid] = tf32r(silu_f(pre));
    }
    __syncthreads();
    if (tid < 64) {
        float accd = be2s[tid];
#pragma unroll 8
        for (int c = 0; c < 64; c++) accd += u_self[c] * W2s[c * 64 + tid];
        m_self[tid] = silu_f(accd);
    }

    const int w  = tid >> 5;
    const int kw = (w & 3) * 16;
    const int jw = (w >> 2) * 64;
    float miacc = 0.f;                 // threads >=128: partial m_i row sum
    float ax = 0.f, ay = 0.f, az = 0.f;

    for (int t = 0; t < 8; t++) {
        const int j0 = t * TJ;
        float* geo = sm + OFF_GEO + (t & 1) * 640;
        float* d2s = geo, *a_s = geo + 128;
        float* dfx = geo + 256, *dfy = geo + 384, *dfz = geo + 512;

        // ---- phase A: uT[c][j] = tf32(silu(pre)) ----
        {
            const int jq = (tid & 31) * 4;
#pragma unroll
            for (int p = 0; p < 8; p++) {
                int c = p * 8 + w;
                float4 pj = *(const float4*)&g_pe_jT[c * M_NODES + j0 + jq];
                float pc = peib[c], wa = w128s[c], wb = w129s[c];
                float4 dd = *(const float4*)&d2s[jq];
                float4 aa = *(const float4*)&a_s[jq];
                float4 r;
                r.x = tf32r(silu_f(pc + pj.x + dd.x * wa + aa.x * wb));
                r.y = tf32r(silu_f(pc + pj.y + dd.y * wa + aa.y * wb));
                r.z = tf32r(silu_f(pc + pj.z + dd.z * wa + aa.z * wb));
                r.w = tf32r(silu_f(pc + pj.w + dd.w * wa + aa.w * wb));
                *(float4*)&uT[c * UP + jq] = r;
            }
        }
        __syncthreads();

        // prefetch next tile geometry into registers (overlaps GEMM B)
        float px0 = 0.f, px1 = 0.f, px2 = 0.f, pa = 0.f;
        const bool pf = (tid < 128) && (t + 1 < 8);
        if (pf) {
            int jn = (t + 1) * TJ + tid;
            px0 = x[jn * 3 + 0]; px1 = x[jn * 3 + 1]; px2 = x[jn * 3 + 2];
            pa = a[i * M_NODES + jn];
        }

        // ---- phase B: mT = tf32(silu(u @ We2 + be2)) via tensor cores ----
        gemm_wmma<true>(W2s, bA2, ones, uT, mT, kw, jw);

        if (pf) {
            float* gn = sm + OFF_GEO + ((t + 1) & 1) * 640;
            float dx = xi0 - px0, dy = xi1 - px1, dz = xi2 - px2;
            gn[256 + tid] = dx; gn[384 + tid] = dy; gn[512 + tid] = dz;
            gn[tid] = dx * dx + dy * dy + dz * dz;
            gn[128 + tid] = pa;
        }
        __syncthreads();

        // ---- phase C: vT = silu(m @ Wx1 + bx1) -> uT buffer ----
        gemm_wmma<false>(Wx1s, bAX, ones, mT, uT, kw, jw);
        __syncthreads();

        // ---- phase D: split work ----
        if (tid < 128) {
            // s_j = bx2 + v[:,j] . wx2 ; self term dies via diff=0
            float s = bx2v;
#pragma unroll 8
            for (int k = 0; k < 64; k++) s += uT[k * UP + tid] * wx2s[k];
            ax += dfx[tid] * s; ay += dfy[tid] * s; az += dfz[tid] * s;
        } else {
            // m_i partial row sums over this tile (includes diagonal; fixed later)
            int idx = tid - 128;
            const float* row = mT + (idx & 63) * UP + (idx >> 6) * 64;
            float s = 0.f;
#pragma unroll
            for (int q = 0; q < 16; q++) {
                float4 v = *(const float4*)(row + q * 4);
                s += (v.x + v.y) + (v.z + v.w);
            }
            miacc += s;
        }
        __syncthreads();
    }

    // ---- reductions (alias uT region, dead now) ----
    float* redm = sm + OFF_UT;          // 128
    float* redx = sm + OFF_UT + 128;    // 384
    if (tid >= 128) redm[tid - 128] = miacc;
    if (tid < 128) { redx[tid] = ax; redx[128 + tid] = ay; redx[256 + tid] = az; }
    __syncthreads();

    float* mis = sm + OFF_GEO;        // reuse as m_i[64]
    float* gs  = sm + OFF_GEO + 64;   // reuse as hidden[64]
    if (tid < 64) {
        mis[tid] = redm[tid] + redm[64 + tid] - m_self[tid];
    }
    if (tid >= 128 && tid < 131) {
        int comp = tid - 128;
        float s = 0.f;
        for (int q = 0; q < 128; q++) s += redx[comp * 128 + q];
        const float C = 1.0f / (float)(M_NODES - 1);
        out[i * 3 + comp] = x[i * 3 + comp] + C * s;
    }
    __syncthreads();

    // ---- phi_h ----
    if (tid < 64) {
        float acc = bh1[tid];
        const float* hr = h + i * 64;
#pragma unroll 4
        for (int c = 0; c < 64; c++) acc += hr[c] * Wh1[c * 64 + tid];
#pragma unroll 4
        for (int c = 0; c < 64; c++) acc += mis[c] * Wh1[(64 + c) * 64 + tid];
        gs[tid] = silu_f(acc);
    }
    __syncthreads();
    if (tid < 64) {
        float acc = bh2[tid];
#pragma unroll 4
        for (int c = 0; c < 64; c++) acc += gs[c] * Wh2[c * 64 + tid];
        out[3 * M_NODES + i * 64 + tid] = acc;
    }
}

extern "C" void kernel_launch(void* const* d_in, const int* in_sizes, int n_in,
                              void* d_out, int out_size) {
    const float* x   = (const float*)d_in[0];
    const float* a   = (const float*)d_in[1];
    const float* h   = (const float*)d_in[2];
    const float* We1 = (const float*)d_in[3];
    const float* be1 = (const float*)d_in[4];
    const float* We2 = (const float*)d_in[5];
    const float* be2 = (const float*)d_in[6];
    const float* Wx1 = (const float*)d_in[7];
    const float* bx1 = (const float*)d_in[8];
    const float* Wx2 = (const float*)d_in[9];
    const float* bx2 = (const float*)d_in[10];
    const float* Wh1 = (const float*)d_in[11];
    const float* bh1 = (const float*)d_in[12];
    const float* Wh2 = (const float*)d_in[13];
    const float* bh2 = (const float*)d_in[14];
    float* out = (float*)d_out;

    cudaFuncSetAttribute(egnn_main, cudaFuncAttributeMaxDynamicSharedMemorySize, SMEM_BYTES);

    pe_kernel<<<(M_NODES * 64) / NTHREADS, NTHREADS>>>(h, We1);
    egnn_main<<<M_NODES, NTHREADS, SMEM_BYTES>>>(
        x, a, h, We1, be1, We2, be2, Wx1, bx1, Wx2, bx2,
        Wh1, bh1, Wh2, bh2, out);
}